// round 8
// baseline (speedup 1.0000x reference)
#include <cuda_runtime.h>
#include <cuda_fp16.h>
#include <cstdint>
#include <cstddef>

// ---------------------------------------------------------------------------
// OCR head on GB300 — Round 8: fp16 mma.sync GEMMs, now with a 3-stage
// cp.async pipeline (prefetch distance 2, wait_group<1>) to close the
// 2-stage wait bubble that capped tensor at ~51%; fused single weight
// conversion kernel. CTA 128x128x64, 4 warps, warp tile 64x64, 2 CTAs/SM.
// ---------------------------------------------------------------------------

#define BATCH 4
#define CDIM 512
#define NDIM 16384
#define KEYD 256

// fp16 buffers
__device__ __half g_featH[33554432];  // feat   [B,512,N]
__device__ __half g_pwH[33554432];    // softmax(feat) [B,512,N]
__device__ __half g_simH[33554432];   // sim    [B,N,512]
__device__ __half g_uH[33554432];     // ctx_up [B,512,N]
__device__ __half g_t1H[16777216];    // t1 [B,256,N]; later attn ctx
__device__ __half g_qH[16777216];     // q  [B,256,N]
__device__ __half g_ctxH[1048576];    // context [B,512,512]
__device__ __half g_c1H[524288];      // [B,256,512]
__device__ __half g_kmH[524288];      // [B,256,512]
__device__ __half g_vH[524288];       // [B,256,512]
__device__ __half g_wH[1179648];      // converted weights (packed)
__device__ float g_split[16777216];   // split-K partials [B*16,512,512]

// ---------------------------------------------------------------------------
__device__ __forceinline__ void mma_f16(float c[4], const uint32_t a[4],
                                        const uint32_t b[2]) {
    asm volatile(
        "mma.sync.aligned.m16n8k16.row.col.f32.f16.f16.f32 "
        "{%0,%1,%2,%3}, {%4,%5,%6,%7}, {%8,%9}, {%0,%1,%2,%3};"
        : "+f"(c[0]), "+f"(c[1]), "+f"(c[2]), "+f"(c[3])
        : "r"(a[0]), "r"(a[1]), "r"(a[2]), "r"(a[3]), "r"(b[0]), "r"(b[1]));
}
__device__ __forceinline__ void cp16(uint32_t dst, const void* src) {
    asm volatile("cp.async.cg.shared.global [%0], [%1], 16;\n"
                 :: "r"(dst), "l"(src));
}
__device__ __forceinline__ void cp_commit() {
    asm volatile("cp.async.commit_group;\n" ::: "memory");
}
template <int N>
__device__ __forceinline__ void cp_wait_group() {
    asm volatile("cp.async.wait_group %0;\n" :: "n"(N) : "memory");
}
__device__ __forceinline__ void cp_wait_all() {
    asm volatile("cp.async.wait_all;\n" ::: "memory");
}
__device__ __forceinline__ void ldsm_x4(uint32_t& r0, uint32_t& r1,
                                        uint32_t& r2, uint32_t& r3,
                                        uint32_t addr) {
    asm volatile("ldmatrix.sync.aligned.m8n8.x4.shared.b16 {%0,%1,%2,%3}, [%4];"
                 : "=r"(r0), "=r"(r1), "=r"(r2), "=r"(r3) : "r"(addr));
}
__device__ __forceinline__ void ldsm_x4_t(uint32_t& r0, uint32_t& r1,
                                          uint32_t& r2, uint32_t& r3,
                                          uint32_t addr) {
    asm volatile("ldmatrix.sync.aligned.m8n8.x4.trans.shared.b16 {%0,%1,%2,%3}, [%4];"
                 : "=r"(r0), "=r"(r1), "=r"(r2), "=r"(r3) : "r"(addr));
}

// ---------------------------------------------------------------------------
// fp16 batched GEMM: C[m,n] = act(alpha * sum_k opA(m,k)*opB(k,n) + bias[m])
//   TA: A stored [K,M] (lda halves) else [M,K]; TB: B stored [N,K] else [K,N].
//   CONCAT (TB=false): k rows >= ksplitB come from B2 (same ldb).
//   outHalf: write __half C, else float C. gridDim.z = batch*nsplit.
// CTA tile 128x128, BK=64 halves, 128 threads, warp tile 64x64, 3-stage pipe.
// Requires M%128==0, N%128==0, K%64==0.
// ---------------------------------------------------------------------------
template <bool TA, bool TB, bool CONCAT>
__global__ void __launch_bounds__(128, 2)
gemm_f16(const __half* __restrict__ A, size_t sA, int lda,
         const __half* __restrict__ B, size_t sB, int ldb,
         const __half* __restrict__ B2, int ksplitB,
         void* __restrict__ Cv, size_t sCz, int ldc,
         const float* __restrict__ bias, float alpha, int doRelu, int outHalf,
         int K, int nsplit) {
    constexpr int SA_ROW = 144;     // [m][k]: 64 halves +8 pad = 144 B
    constexpr int SKM_ROW = 272;    // [k][m]/[k][n]: 128 halves +8 pad = 272 B
    constexpr int ASZ = TA ? 64 * SKM_ROW : 128 * SA_ROW;
    constexpr int BSZ = TB ? 128 * SA_ROW : 64 * SKM_ROW;
    constexpr int STG = ASZ + BSZ;
    constexpr int NS = 3;

    extern __shared__ __align__(16) char smem[];
    uint32_t base = (uint32_t)__cvta_generic_to_shared(smem);

    int z = blockIdx.z;
    int b = z / nsplit;
    int sidx = z - b * nsplit;
    int kchunk = K / nsplit;
    int kbeg = sidx * kchunk;
    int niter = kchunk >> 6;

    const __half* Ab = A + (size_t)b * sA;
    const __half* Bb = B + (size_t)b * sB;
    const __half* B2b = CONCAT ? (B2 + (size_t)b * sB) : (const __half*)nullptr;

    int m0 = blockIdx.y * 128;
    int n0 = blockIdx.x * 128;
    int tid = threadIdx.x;
    int warp = tid >> 5, lane = tid & 31;
    int g = lane >> 2, r = lane & 3;
    int wm = warp & 1, wn = warp >> 1;
    int warp_m0 = wm * 64, warp_n0 = wn * 64;

    // ldmatrix per-lane selectors
    int mo8 = (lane & 7) + ((lane >> 3) & 1) * 8;  // non-trans row
    int khalf = lane >> 4;                         // non-trans col half (16B)
    int kq = (lane & 7) + ((lane >> 4) & 1) * 8;   // trans k-row within 16
    int chalf = (lane >> 3) & 1;                   // trans col half (16B)

    float acc[4][8][4];
    #pragma unroll
    for (int i = 0; i < 4; i++)
        #pragma unroll
        for (int j = 0; j < 8; j++)
            #pragma unroll
            for (int e = 0; e < 4; e++) acc[i][j][e] = 0.f;

    auto prefetch = [&](int st, int k0) {
        uint32_t ab = base + st * STG;
        uint32_t bb = ab + ASZ;
        if (TA) {
            #pragma unroll
            for (int p = 0; p < 8; p++) {
                int idx = tid + p * 128;
                int row = idx >> 4, mc = idx & 15;
                cp16(ab + row * SKM_ROW + mc * 16,
                     Ab + (size_t)(k0 + row) * lda + m0 + mc * 8);
            }
        } else {
            #pragma unroll
            for (int p = 0; p < 8; p++) {
                int idx = tid + p * 128;
                int row = idx >> 3, kc = idx & 7;
                cp16(ab + row * SA_ROW + kc * 16,
                     Ab + (size_t)(m0 + row) * lda + k0 + kc * 8);
            }
        }
        if (TB) {
            #pragma unroll
            for (int p = 0; p < 8; p++) {
                int idx = tid + p * 128;
                int row = idx >> 3, kc = idx & 7;
                cp16(bb + row * SA_ROW + kc * 16,
                     Bb + (size_t)(n0 + row) * ldb + k0 + kc * 8);
            }
        } else {
            #pragma unroll
            for (int p = 0; p < 8; p++) {
                int idx = tid + p * 128;
                int row = idx >> 4, nc = idx & 15;
                int kr = k0 + row;
                const __half* src;
                if (CONCAT && kr >= ksplitB)
                    src = B2b + (size_t)(kr - ksplitB) * ldb + n0 + nc * 8;
                else
                    src = Bb + (size_t)kr * ldb + n0 + nc * 8;
                cp16(bb + row * SKM_ROW + nc * 16, src);
            }
        }
        cp_commit();
    };

    // prologue: two stages in flight
    prefetch(0, kbeg);
    if (niter > 1) prefetch(1, kbeg + 64); else cp_commit();

    for (int it = 0; it < niter; it++) {
        int st = it % NS;
        cp_wait_group<1>();          // stage `it` complete
        __syncthreads();
        if (it + 2 < niter) prefetch((it + 2) % NS, kbeg + (it + 2) * 64);
        else cp_commit();

        uint32_t ab = base + st * STG;
        uint32_t bb = ab + ASZ;

        #pragma unroll
        for (int ks = 0; ks < 4; ks++) {   // 4 x k16 per 64-half stage
            uint32_t af[4][4], bf[8][2];
            if (TA) {
                #pragma unroll
                for (int i = 0; i < 4; i++) {
                    uint32_t addr = ab + (ks * 16 + kq) * SKM_ROW +
                                    (warp_m0 + i * 16) * 2 + chalf * 16;
                    ldsm_x4_t(af[i][0], af[i][1], af[i][2], af[i][3], addr);
                }
            } else {
                #pragma unroll
                for (int i = 0; i < 4; i++) {
                    uint32_t addr = ab + (warp_m0 + i * 16 + mo8) * SA_ROW +
                                    ks * 32 + khalf * 16;
                    ldsm_x4(af[i][0], af[i][1], af[i][2], af[i][3], addr);
                }
            }
            if (TB) {
                #pragma unroll
                for (int jj = 0; jj < 4; jj++) {
                    uint32_t addr = bb + (warp_n0 + jj * 16 + mo8) * SA_ROW +
                                    ks * 32 + khalf * 16;
                    ldsm_x4(bf[2 * jj][0], bf[2 * jj + 1][0],
                            bf[2 * jj][1], bf[2 * jj + 1][1], addr);
                }
            } else {
                #pragma unroll
                for (int jj = 0; jj < 4; jj++) {
                    uint32_t addr = bb + (ks * 16 + kq) * SKM_ROW +
                                    (warp_n0 + jj * 16) * 2 + chalf * 16;
                    ldsm_x4_t(bf[2 * jj][0], bf[2 * jj + 1][0],
                              bf[2 * jj][1], bf[2 * jj + 1][1], addr);
                }
            }
            #pragma unroll
            for (int i = 0; i < 4; i++)
                #pragma unroll
                for (int j = 0; j < 8; j++)
                    mma_f16(acc[i][j], af[i], bf[j]);
        }
        // no trailing syncthreads: slot st is only overwritten in iteration
        // it+1 AFTER its top-of-loop __syncthreads, which orders all warps'
        // compute of stage st before the prefetch that reuses it.
    }

    cp_wait_all();

    // ---- epilogue
    __half* Ch = (__half*)Cv + (size_t)z * sCz;
    float* Cf = (float*)Cv + (size_t)z * sCz;
    #pragma unroll
    for (int i = 0; i < 4; i++) {
        int m = m0 + warp_m0 + i * 16 + g;
        float bv0 = bias ? bias[m] : 0.f;
        float bv8 = bias ? bias[m + 8] : 0.f;
        #pragma unroll
        for (int j = 0; j < 8; j++) {
            int n = n0 + warp_n0 + j * 8 + 2 * r;
            float x0 = acc[i][j][0] * alpha + bv0;
            float x1 = acc[i][j][1] * alpha + bv0;
            float x2 = acc[i][j][2] * alpha + bv8;
            float x3 = acc[i][j][3] * alpha + bv8;
            if (doRelu) {
                x0 = fmaxf(x0, 0.f); x1 = fmaxf(x1, 0.f);
                x2 = fmaxf(x2, 0.f); x3 = fmaxf(x3, 0.f);
            }
            if (outHalf) {
                *(__half2*)&Ch[(size_t)m * ldc + n] = __floats2half2_rn(x0, x1);
                *(__half2*)&Ch[(size_t)(m + 8) * ldc + n] = __floats2half2_rn(x2, x3);
            } else {
                *(float2*)&Cf[(size_t)m * ldc + n] = make_float2(x0, x1);
                *(float2*)&Cf[(size_t)(m + 8) * ldc + n] = make_float2(x2, x3);
            }
        }
    }
}

// ---------------------------------------------------------------------------
// softmax over rows of 16384: emits fp16 softmax AND fp16 copy of input.
__global__ void softmax_rows16k(const float* __restrict__ x,
                                __half* __restrict__ pwout,
                                __half* __restrict__ xh) {
    extern __shared__ float srow[];
    __shared__ float red[256];
    const int NC = NDIM;
    size_t row = blockIdx.x;
    const float* xr = x + row * (size_t)NC;
    __half* pwr = pwout + row * (size_t)NC;
    __half* xhr = xh + row * (size_t)NC;
    int tid = threadIdx.x;

    float m = -3.4e38f;
    for (int i = tid * 4; i < NC; i += 1024) {
        float4 v = *(const float4*)&xr[i];
        *(float4*)&srow[i] = v;
        *(__half2*)&xhr[i] = __floats2half2_rn(v.x, v.y);
        *(__half2*)&xhr[i + 2] = __floats2half2_rn(v.z, v.w);
        m = fmaxf(m, fmaxf(fmaxf(v.x, v.y), fmaxf(v.z, v.w)));
    }
    red[tid] = m;
    __syncthreads();
    for (int s = 128; s > 0; s >>= 1) {
        if (tid < s) red[tid] = fmaxf(red[tid], red[tid + s]);
        __syncthreads();
    }
    m = red[0];
    __syncthreads();

    float sum = 0.f;
    for (int i = tid * 4; i < NC; i += 1024) {
        float4 v = *(float4*)&srow[i];
        v.x = __expf(v.x - m); v.y = __expf(v.y - m);
        v.z = __expf(v.z - m); v.w = __expf(v.w - m);
        *(float4*)&srow[i] = v;
        sum += v.x + v.y + v.z + v.w;
    }
    red[tid] = sum;
    __syncthreads();
    for (int s = 128; s > 0; s >>= 1) {
        if (tid < s) red[tid] += red[tid + s];
        __syncthreads();
    }
    float inv = 1.f / red[0];

    for (int i = tid * 4; i < NC; i += 1024) {
        float4 v = *(float4*)&srow[i];
        *(__half2*)&pwr[i] = __floats2half2_rn(v.x * inv, v.y * inv);
        *(__half2*)&pwr[i + 2] = __floats2half2_rn(v.z * inv, v.w * inv);
    }
}

// softmax over rows of 512 fp16 (in place). grid = B*N, 128 threads.
__global__ void softmax_k512h(__half* __restrict__ sim) {
    __shared__ float redm[4];
    __shared__ float reds[4];
    size_t row = blockIdx.x;
    __half2* rp = (__half2*)(sim + row * 512);
    int tid = threadIdx.x;

    __half2 h0 = rp[tid * 2], h1 = rp[tid * 2 + 1];
    float2 f0 = __half22float2(h0), f1 = __half22float2(h1);
    float m = fmaxf(fmaxf(f0.x, f0.y), fmaxf(f1.x, f1.y));
    #pragma unroll
    for (int o = 16; o > 0; o >>= 1)
        m = fmaxf(m, __shfl_xor_sync(0xffffffffu, m, o));
    if ((tid & 31) == 0) redm[tid >> 5] = m;
    __syncthreads();
    m = fmaxf(fmaxf(redm[0], redm[1]), fmaxf(redm[2], redm[3]));

    float e0 = __expf(f0.x - m), e1 = __expf(f0.y - m);
    float e2 = __expf(f1.x - m), e3 = __expf(f1.y - m);
    float s = e0 + e1 + e2 + e3;
    #pragma unroll
    for (int o = 16; o > 0; o >>= 1)
        s += __shfl_xor_sync(0xffffffffu, s, o);
    if ((tid & 31) == 0) reds[tid >> 5] = s;
    __syncthreads();
    float inv = 1.f / (reds[0] + reds[1] + reds[2] + reds[3]);

    rp[tid * 2] = __floats2half2_rn(e0 * inv, e1 * inv);
    rp[tid * 2 + 1] = __floats2half2_rn(e2 * inv, e3 * inv);
}

// Sum fp32 split-K partials -> fp16
__global__ void reduce_split(const float* __restrict__ in,
                             __half* __restrict__ out, int per, int nsplit,
                             size_t total) {
    size_t i = (size_t)blockIdx.x * blockDim.x + threadIdx.x;
    if (i >= total) return;
    size_t b = i / per;
    size_t r = i - b * per;
    const float* src = in + b * (size_t)nsplit * per + r;
    float s = 0.f;
    for (int ss = 0; ss < nsplit; ss++) s += src[(size_t)ss * per];
    out[i] = __float2half_rn(s);
}

// Fused fp32->fp16 conversion of all 7 weight tensors (packed layout).
__global__ void convert_weights(const float* __restrict__ wp1,
                                const float* __restrict__ wp2,
                                const float* __restrict__ wo1,
                                const float* __restrict__ wo2,
                                const float* __restrict__ wd,
                                const float* __restrict__ wu,
                                const float* __restrict__ wout,
                                __half* __restrict__ out) {
    int i = (blockIdx.x * blockDim.x + threadIdx.x) * 4;
    if (i >= 1179648) return;
    const float* src;
    int local;
    if (i < 131072)      { src = wp1;  local = i; }
    else if (i < 196608) { src = wp2;  local = i - 131072; }
    else if (i < 327680) { src = wo1;  local = i - 196608; }
    else if (i < 393216) { src = wo2;  local = i - 327680; }
    else if (i < 524288) { src = wd;   local = i - 393216; }
    else if (i < 655360) { src = wu;   local = i - 524288; }
    else                 { src = wout; local = i - 655360; }
    float4 v = *(const float4*)&src[local];
    *(__half2*)&out[i] = __floats2half2_rn(v.x, v.y);
    *(__half2*)&out[i + 2] = __floats2half2_rn(v.z, v.w);
}

// ---------------------------------------------------------------------------
// smem sizes (bytes, 3 stages)
static constexpr int SM_FF = 3 * (128 * 144 + 64 * 272);   // 107520
static constexpr int SM_FT = 3 * (128 * 144 + 128 * 144);  // 110592
static constexpr int SM_TF = 3 * (64 * 272 + 64 * 272);    // 104448

extern "C" void kernel_launch(void* const* d_in, const int* in_sizes, int n_in,
                              void* d_out, int out_size) {
    (void)in_sizes; (void)n_in; (void)out_size;
    const float* feat = (const float*)d_in[0];
    const float* wp1 = (const float*)d_in[2];
    const float* bp1 = (const float*)d_in[3];
    const float* wp2 = (const float*)d_in[4];
    const float* bp2 = (const float*)d_in[5];
    const float* wo1 = (const float*)d_in[6];
    const float* bo1 = (const float*)d_in[7];
    const float* wo2 = (const float*)d_in[8];
    const float* bo2 = (const float*)d_in[9];
    const float* wd  = (const float*)d_in[10];
    const float* bd  = (const float*)d_in[11];
    const float* wu  = (const float*)d_in[12];
    const float* bu  = (const float*)d_in[13];
    const float* wout = (const float*)d_in[14];
    const float* bout = (const float*)d_in[15];
    float* outp = (float*)d_out;

    __half *featH, *pwH, *simH, *uH, *t1H, *qH, *ctxH, *c1H, *kmH, *vH, *wH;
    float* splitF;
    cudaGetSymbolAddress((void**)&featH, g_featH);
    cudaGetSymbolAddress((void**)&pwH, g_pwH);
    cudaGetSymbolAddress((void**)&simH, g_simH);
    cudaGetSymbolAddress((void**)&uH, g_uH);
    cudaGetSymbolAddress((void**)&t1H, g_t1H);
    cudaGetSymbolAddress((void**)&qH, g_qH);
    cudaGetSymbolAddress((void**)&ctxH, g_ctxH);
    cudaGetSymbolAddress((void**)&c1H, g_c1H);
    cudaGetSymbolAddress((void**)&kmH, g_kmH);
    cudaGetSymbolAddress((void**)&vH, g_vH);
    cudaGetSymbolAddress((void**)&wH, g_wH);
    cudaGetSymbolAddress((void**)&splitF, g_split);
    __half* wp1H = wH;               // 131072
    __half* wp2H = wH + 131072;      // 65536
    __half* wo1H = wH + 196608;      // 131072
    __half* wo2H = wH + 327680;      // 65536
    __half* wdH  = wH + 393216;      // 131072
    __half* wuH  = wH + 524288;      // 131072
    __half* woutH = wH + 655360;     // 524288

    const size_t sBN = (size_t)CDIM * NDIM;
    const size_t sKN = (size_t)KEYD * NDIM;
    const size_t sCC = (size_t)CDIM * CDIM;
    const size_t sKC = (size_t)KEYD * CDIM;

    cudaFuncSetAttribute(softmax_rows16k,
                         cudaFuncAttributeMaxDynamicSharedMemorySize, 65536);
    cudaFuncSetAttribute(gemm_f16<false, false, false>,
                         cudaFuncAttributeMaxDynamicSharedMemorySize, SM_FF);
    cudaFuncSetAttribute(gemm_f16<false, false, true>,
                         cudaFuncAttributeMaxDynamicSharedMemorySize, SM_FF);
    cudaFuncSetAttribute(gemm_f16<false, true, false>,
                         cudaFuncAttributeMaxDynamicSharedMemorySize, SM_FT);
    cudaFuncSetAttribute(gemm_f16<true, false, false>,
                         cudaFuncAttributeMaxDynamicSharedMemorySize, SM_TF);

    // 0) all weight conversions in one launch
    convert_weights<<<1152, 256>>>(wp1, wp2, wo1, wo2, wd, wu, wout, wH);

    // 1) pwH = softmax(feat rows); featH = fp16(feat)
    softmax_rows16k<<<BATCH * CDIM, 256, 65536>>>(feat, pwH, featH);

    // 2) context partials = featH * pwH^T (split-K=16) -> splitF (fp32)
    gemm_f16<false, true, false><<<dim3(4, 4, BATCH * 16), 128, SM_FT>>>(
        featH, sBN, NDIM, pwH, sBN, NDIM, nullptr, 0,
        splitF, sCC, CDIM, nullptr, 1.f, 0, 0, NDIM, 16);
    // 3) reduce -> ctxH
    {
        size_t total = (size_t)BATCH * sCC;
        reduce_split<<<(unsigned)((total + 255) / 256), 256>>>(
            splitF, ctxH, (int)sCC, 16, total);
    }
    // 4) t1 = relu(wp1 @ x + bp1) -> t1H [B,256,N]
    gemm_f16<false, false, false><<<dim3(128, 2, BATCH), 128, SM_FF>>>(
        wp1H, 0, CDIM, featH, sBN, NDIM, nullptr, 0,
        t1H, sKN, NDIM, bp1, 1.f, 1, 1, CDIM, 1);
    // 5) q = relu(wp2 @ t1 + bp2) -> qH [B,256,N]
    gemm_f16<false, false, false><<<dim3(128, 2, BATCH), 128, SM_FF>>>(
        wp2H, 0, KEYD, t1H, sKN, NDIM, nullptr, 0,
        qH, sKN, NDIM, bp2, 1.f, 1, 1, KEYD, 1);
    // 6) c1 = relu(wo1 @ context + bo1) -> c1H [B,256,512]
    gemm_f16<false, false, false><<<dim3(4, 2, BATCH), 128, SM_FF>>>(
        wo1H, 0, CDIM, ctxH, sCC, CDIM, nullptr, 0,
        c1H, sKC, CDIM, bo1, 1.f, 1, 1, CDIM, 1);
    // 7) km = relu(wo2 @ c1 + bo2) -> kmH [B,256,512]
    gemm_f16<false, false, false><<<dim3(4, 2, BATCH), 128, SM_FF>>>(
        wo2H, 0, KEYD, c1H, sKC, CDIM, nullptr, 0,
        kmH, sKC, CDIM, bo2, 1.f, 1, 1, KEYD, 1);
    // 8) v = relu(wd @ context + bd) -> vH [B,256,512]
    gemm_f16<false, false, false><<<dim3(4, 2, BATCH), 128, SM_FF>>>(
        wdH, 0, CDIM, ctxH, sCC, CDIM, nullptr, 0,
        vH, sKC, CDIM, bd, 1.f, 1, 1, CDIM, 1);
    // 9) sim = (q^T @ km) * KEY^-0.5 -> simH [B,N,512]
    gemm_f16<true, false, false><<<dim3(4, 128, BATCH), 128, SM_TF>>>(
        qH, sKN, NDIM, kmH, sKC, CDIM, nullptr, 0,
        simH, sBN, CDIM, nullptr, 0.0625f, 0, 1, KEYD, 1);
    // 10) softmax over K=512 (in place, fp16)
    softmax_k512h<<<BATCH * NDIM, 128>>>(simH);
    // 11) attn ctx = v @ sim^T -> t1H [B,256,N]
    gemm_f16<false, true, false><<<dim3(128, 2, BATCH), 128, SM_FT>>>(
        vH, sKC, CDIM, simH, sBN, CDIM, nullptr, 0,
        t1H, sKN, NDIM, nullptr, 1.f, 0, 1, CDIM, 1);
    // 12) ctx_up = relu(wu @ attn_ctx + bu) -> uH [B,512,N]
    gemm_f16<false, false, false><<<dim3(128, 4, BATCH), 128, SM_FF>>>(
        wuH, 0, KEYD, t1H, sKN, NDIM, nullptr, 0,
        uH, sBN, NDIM, bu, 1.f, 1, 1, KEYD, 1);
    // 13) out = relu(wout @ concat(ctx_up, x) + bout) -> d_out (fp32)
    gemm_f16<false, false, true><<<dim3(128, 4, BATCH), 128, SM_FF>>>(
        woutH, 0, 2 * CDIM, uH, sBN, NDIM, featH, CDIM,
        outp, sBN, NDIM, bout, 1.f, 1, 0, 2 * CDIM, 1);
}

// round 9
// speedup vs baseline: 1.0025x; 1.0025x over previous
#include <cuda_runtime.h>
#include <cuda_fp16.h>
#include <cstdint>
#include <cstddef>

// ---------------------------------------------------------------------------
// OCR head on GB300 — Round 9: fp16 mma.sync GEMMs, 2-stage cp.async pipe
// (measured best), NEW: explicit ldmatrix fragment double-buffering across
// k16 blocks to hide LDSM->HMMA latency (the stall source left after R8
// falsified the gmem-latency theory). Context GEMM split-K 16->4 (1 wave).
// ---------------------------------------------------------------------------

#define BATCH 4
#define CDIM 512
#define NDIM 16384
#define KEYD 256

// fp16 buffers
__device__ __half g_featH[33554432];  // feat   [B,512,N]
__device__ __half g_pwH[33554432];    // softmax(feat) [B,512,N]
__device__ __half g_simH[33554432];   // sim    [B,N,512]
__device__ __half g_uH[33554432];     // ctx_up [B,512,N]
__device__ __half g_t1H[16777216];    // t1 [B,256,N]; later attn ctx
__device__ __half g_qH[16777216];     // q  [B,256,N]
__device__ __half g_ctxH[1048576];    // context [B,512,512]
__device__ __half g_c1H[524288];      // [B,256,512]
__device__ __half g_kmH[524288];      // [B,256,512]
__device__ __half g_vH[524288];       // [B,256,512]
__device__ __half g_wH[1179648];      // converted weights (packed)
__device__ float g_split[16777216];   // split-K partials

// ---------------------------------------------------------------------------
__device__ __forceinline__ void mma_f16(float c[4], const uint32_t a[4],
                                        const uint32_t b[2]) {
    asm volatile(
        "mma.sync.aligned.m16n8k16.row.col.f32.f16.f16.f32 "
        "{%0,%1,%2,%3}, {%4,%5,%6,%7}, {%8,%9}, {%0,%1,%2,%3};"
        : "+f"(c[0]), "+f"(c[1]), "+f"(c[2]), "+f"(c[3])
        : "r"(a[0]), "r"(a[1]), "r"(a[2]), "r"(a[3]), "r"(b[0]), "r"(b[1]));
}
__device__ __forceinline__ void cp16(uint32_t dst, const void* src) {
    asm volatile("cp.async.cg.shared.global [%0], [%1], 16;\n"
                 :: "r"(dst), "l"(src));
}
__device__ __forceinline__ void cp_commit() {
    asm volatile("cp.async.commit_group;\n" ::: "memory");
}
__device__ __forceinline__ void cp_wait0() {
    asm volatile("cp.async.wait_group 0;\n" ::: "memory");
}
__device__ __forceinline__ void cp_wait_all() {
    asm volatile("cp.async.wait_all;\n" ::: "memory");
}
__device__ __forceinline__ void ldsm_x4(uint32_t& r0, uint32_t& r1,
                                        uint32_t& r2, uint32_t& r3,
                                        uint32_t addr) {
    asm volatile("ldmatrix.sync.aligned.m8n8.x4.shared.b16 {%0,%1,%2,%3}, [%4];"
                 : "=r"(r0), "=r"(r1), "=r"(r2), "=r"(r3) : "r"(addr));
}
__device__ __forceinline__ void ldsm_x4_t(uint32_t& r0, uint32_t& r1,
                                          uint32_t& r2, uint32_t& r3,
                                          uint32_t addr) {
    asm volatile("ldmatrix.sync.aligned.m8n8.x4.trans.shared.b16 {%0,%1,%2,%3}, [%4];"
                 : "=r"(r0), "=r"(r1), "=r"(r2), "=r"(r3) : "r"(addr));
}

// ---------------------------------------------------------------------------
// fp16 batched GEMM: C[m,n] = act(alpha * sum_k opA(m,k)*opB(k,n) + bias[m])
//   TA: A stored [K,M] (lda halves) else [M,K]; TB: B stored [N,K] else [K,N].
//   CONCAT (TB=false): k rows >= ksplitB come from B2 (same ldb).
//   outHalf: write __half C, else float C. gridDim.z = batch*nsplit.
// CTA tile 128x128, BK=64 halves, 128 threads, warp tile 64x64, 2-stage
// cp.async pipe + 2-deep ldmatrix fragment pipeline.
// Requires M%128==0, N%128==0, K%64==0.
// ---------------------------------------------------------------------------
template <bool TA, bool TB, bool CONCAT>
__global__ void __launch_bounds__(128, 2)
gemm_f16(const __half* __restrict__ A, size_t sA, int lda,
         const __half* __restrict__ B, size_t sB, int ldb,
         const __half* __restrict__ B2, int ksplitB,
         void* __restrict__ Cv, size_t sCz, int ldc,
         const float* __restrict__ bias, float alpha, int doRelu, int outHalf,
         int K, int nsplit) {
    constexpr int SA_ROW = 144;     // [m][k]: 64 halves +8 pad = 144 B
    constexpr int SKM_ROW = 272;    // [k][m]/[k][n]: 128 halves +8 pad = 272 B
    constexpr int ASZ = TA ? 64 * SKM_ROW : 128 * SA_ROW;
    constexpr int BSZ = TB ? 128 * SA_ROW : 64 * SKM_ROW;
    constexpr int STG = ASZ + BSZ;

    extern __shared__ __align__(16) char smem[];
    uint32_t base = (uint32_t)__cvta_generic_to_shared(smem);

    int z = blockIdx.z;
    int b = z / nsplit;
    int sidx = z - b * nsplit;
    int kchunk = K / nsplit;
    int kbeg = sidx * kchunk;
    int niter = kchunk >> 6;

    const __half* Ab = A + (size_t)b * sA;
    const __half* Bb = B + (size_t)b * sB;
    const __half* B2b = CONCAT ? (B2 + (size_t)b * sB) : (const __half*)nullptr;

    int m0 = blockIdx.y * 128;
    int n0 = blockIdx.x * 128;
    int tid = threadIdx.x;
    int warp = tid >> 5, lane = tid & 31;
    int g = lane >> 2, r = lane & 3;
    int wm = warp & 1, wn = warp >> 1;
    int warp_m0 = wm * 64, warp_n0 = wn * 64;

    // ldmatrix per-lane selectors
    int mo8 = (lane & 7) + ((lane >> 3) & 1) * 8;  // non-trans row
    int khalf = lane >> 4;                         // non-trans col half (16B)
    int kq = (lane & 7) + ((lane >> 4) & 1) * 8;   // trans k-row within 16
    int chalf = (lane >> 3) & 1;                   // trans col half (16B)

    float acc[4][8][4];
    #pragma unroll
    for (int i = 0; i < 4; i++)
        #pragma unroll
        for (int j = 0; j < 8; j++)
            #pragma unroll
            for (int e = 0; e < 4; e++) acc[i][j][e] = 0.f;

    auto prefetch = [&](int st, int k0) {
        uint32_t ab = base + st * STG;
        uint32_t bb = ab + ASZ;
        if (TA) {
            #pragma unroll
            for (int p = 0; p < 8; p++) {
                int idx = tid + p * 128;
                int row = idx >> 4, mc = idx & 15;
                cp16(ab + row * SKM_ROW + mc * 16,
                     Ab + (size_t)(k0 + row) * lda + m0 + mc * 8);
            }
        } else {
            #pragma unroll
            for (int p = 0; p < 8; p++) {
                int idx = tid + p * 128;
                int row = idx >> 3, kc = idx & 7;
                cp16(ab + row * SA_ROW + kc * 16,
                     Ab + (size_t)(m0 + row) * lda + k0 + kc * 8);
            }
        }
        if (TB) {
            #pragma unroll
            for (int p = 0; p < 8; p++) {
                int idx = tid + p * 128;
                int row = idx >> 3, kc = idx & 7;
                cp16(bb + row * SA_ROW + kc * 16,
                     Bb + (size_t)(n0 + row) * ldb + k0 + kc * 8);
            }
        } else {
            #pragma unroll
            for (int p = 0; p < 8; p++) {
                int idx = tid + p * 128;
                int row = idx >> 4, nc = idx & 15;
                int kr = k0 + row;
                const __half* src;
                if (CONCAT && kr >= ksplitB)
                    src = B2b + (size_t)(kr - ksplitB) * ldb + n0 + nc * 8;
                else
                    src = Bb + (size_t)kr * ldb + n0 + nc * 8;
                cp16(bb + row * SKM_ROW + nc * 16, src);
            }
        }
        cp_commit();
    };

    prefetch(0, kbeg);

    // fragment double-buffers
    uint32_t af[2][4][4], bf[2][8][2];

    for (int it = 0; it < niter; it++) {
        int st = it & 1;
        cp_wait0();
        __syncthreads();
        if (it + 1 < niter) prefetch(st ^ 1, kbeg + (it + 1) * 64);

        uint32_t ab = base + st * STG;
        uint32_t bb = ab + ASZ;

        // load fragments for a given k16 block into buffer fb
        auto load_frags = [&](int fb, int ks) {
            if (TA) {
                #pragma unroll
                for (int i = 0; i < 4; i++) {
                    uint32_t addr = ab + (ks * 16 + kq) * SKM_ROW +
                                    (warp_m0 + i * 16) * 2 + chalf * 16;
                    ldsm_x4_t(af[fb][i][0], af[fb][i][1],
                              af[fb][i][2], af[fb][i][3], addr);
                }
            } else {
                #pragma unroll
                for (int i = 0; i < 4; i++) {
                    uint32_t addr = ab + (warp_m0 + i * 16 + mo8) * SA_ROW +
                                    ks * 32 + khalf * 16;
                    ldsm_x4(af[fb][i][0], af[fb][i][1],
                            af[fb][i][2], af[fb][i][3], addr);
                }
            }
            if (TB) {
                #pragma unroll
                for (int jj = 0; jj < 4; jj++) {
                    uint32_t addr = bb + (warp_n0 + jj * 16 + mo8) * SA_ROW +
                                    ks * 32 + khalf * 16;
                    ldsm_x4(bf[fb][2 * jj][0], bf[fb][2 * jj + 1][0],
                            bf[fb][2 * jj][1], bf[fb][2 * jj + 1][1], addr);
                }
            } else {
                #pragma unroll
                for (int jj = 0; jj < 4; jj++) {
                    uint32_t addr = bb + (ks * 16 + kq) * SKM_ROW +
                                    (warp_n0 + jj * 16) * 2 + chalf * 16;
                    ldsm_x4_t(bf[fb][2 * jj][0], bf[fb][2 * jj + 1][0],
                              bf[fb][2 * jj][1], bf[fb][2 * jj + 1][1], addr);
                }
            }
        };

        load_frags(0, 0);
        #pragma unroll
        for (int ks = 0; ks < 4; ks++) {
            int cur = ks & 1;
            if (ks < 3) load_frags(cur ^ 1, ks + 1);  // overlap with HMMAs
            #pragma unroll
            for (int i = 0; i < 4; i++)
                #pragma unroll
                for (int j = 0; j < 8; j++)
                    mma_f16(acc[i][j], af[cur][i], bf[cur][j]);
        }
        __syncthreads();
    }

    cp_wait_all();

    // ---- epilogue
    __half* Ch = (__half*)Cv + (size_t)z * sCz;
    float* Cf = (float*)Cv + (size_t)z * sCz;
    #pragma unroll
    for (int i = 0; i < 4; i++) {
        int m = m0 + warp_m0 + i * 16 + g;
        float bv0 = bias ? bias[m] : 0.f;
        float bv8 = bias ? bias[m + 8] : 0.f;
        #pragma unroll
        for (int j = 0; j < 8; j++) {
            int n = n0 + warp_n0 + j * 8 + 2 * r;
            float x0 = acc[i][j][0] * alpha + bv0;
            float x1 = acc[i][j][1] * alpha + bv0;
            float x2 = acc[i][j][2] * alpha + bv8;
            float x3 = acc[i][j][3] * alpha + bv8;
            if (doRelu) {
                x0 = fmaxf(x0, 0.f); x1 = fmaxf(x1, 0.f);
                x2 = fmaxf(x2, 0.f); x3 = fmaxf(x3, 0.f);
            }
            if (outHalf) {
                *(__half2*)&Ch[(size_t)m * ldc + n] = __floats2half2_rn(x0, x1);
                *(__half2*)&Ch[(size_t)(m + 8) * ldc + n] = __floats2half2_rn(x2, x3);
            } else {
                *(float2*)&Cf[(size_t)m * ldc + n] = make_float2(x0, x1);
                *(float2*)&Cf[(size_t)(m + 8) * ldc + n] = make_float2(x2, x3);
            }
        }
    }
}

// ---------------------------------------------------------------------------
// softmax over rows of 16384: emits fp16 softmax AND fp16 copy of input.
__global__ void softmax_rows16k(const float* __restrict__ x,
                                __half* __restrict__ pwout,
                                __half* __restrict__ xh) {
    extern __shared__ float srow[];
    __shared__ float red[256];
    const int NC = NDIM;
    size_t row = blockIdx.x;
    const float* xr = x + row * (size_t)NC;
    __half* pwr = pwout + row * (size_t)NC;
    __half* xhr = xh + row * (size_t)NC;
    int tid = threadIdx.x;

    float m = -3.4e38f;
    for (int i = tid * 4; i < NC; i += 1024) {
        float4 v = *(const float4*)&xr[i];
        *(float4*)&srow[i] = v;
        *(__half2*)&xhr[i] = __floats2half2_rn(v.x, v.y);
        *(__half2*)&xhr[i + 2] = __floats2half2_rn(v.z, v.w);
        m = fmaxf(m, fmaxf(fmaxf(v.x, v.y), fmaxf(v.z, v.w)));
    }
    red[tid] = m;
    __syncthreads();
    for (int s = 128; s > 0; s >>= 1) {
        if (tid < s) red[tid] = fmaxf(red[tid], red[tid + s]);
        __syncthreads();
    }
    m = red[0];
    __syncthreads();

    float sum = 0.f;
    for (int i = tid * 4; i < NC; i += 1024) {
        float4 v = *(float4*)&srow[i];
        v.x = __expf(v.x - m); v.y = __expf(v.y - m);
        v.z = __expf(v.z - m); v.w = __expf(v.w - m);
        *(float4*)&srow[i] = v;
        sum += v.x + v.y + v.z + v.w;
    }
    red[tid] = sum;
    __syncthreads();
    for (int s = 128; s > 0; s >>= 1) {
        if (tid < s) red[tid] += red[tid + s];
        __syncthreads();
    }
    float inv = 1.f / red[0];

    for (int i = tid * 4; i < NC; i += 1024) {
        float4 v = *(float4*)&srow[i];
        *(__half2*)&pwr[i] = __floats2half2_rn(v.x * inv, v.y * inv);
        *(__half2*)&pwr[i + 2] = __floats2half2_rn(v.z * inv, v.w * inv);
    }
}

// softmax over rows of 512 fp16 (in place). grid = B*N, 128 threads.
__global__ void softmax_k512h(__half* __restrict__ sim) {
    __shared__ float redm[4];
    __shared__ float reds[4];
    size_t row = blockIdx.x;
    __half2* rp = (__half2*)(sim + row * 512);
    int tid = threadIdx.x;

    __half2 h0 = rp[tid * 2], h1 = rp[tid * 2 + 1];
    float2 f0 = __half22float2(h0), f1 = __half22float2(h1);
    float m = fmaxf(fmaxf(f0.x, f0.y), fmaxf(f1.x, f1.y));
    #pragma unroll
    for (int o = 16; o > 0; o >>= 1)
        m = fmaxf(m, __shfl_xor_sync(0xffffffffu, m, o));
    if ((tid & 31) == 0) redm[tid >> 5] = m;
    __syncthreads();
    m = fmaxf(fmaxf(redm[0], redm[1]), fmaxf(redm[2], redm[3]));

    float e0 = __expf(f0.x - m), e1 = __expf(f0.y - m);
    float e2 = __expf(f1.x - m), e3 = __expf(f1.y - m);
    float s = e0 + e1 + e2 + e3;
    #pragma unroll
    for (int o = 16; o > 0; o >>= 1)
        s += __shfl_xor_sync(0xffffffffu, s, o);
    if ((tid & 31) == 0) reds[tid >> 5] = s;
    __syncthreads();
    float inv = 1.f / (reds[0] + reds[1] + reds[2] + reds[3]);

    rp[tid * 2] = __floats2half2_rn(e0 * inv, e1 * inv);
    rp[tid * 2 + 1] = __floats2half2_rn(e2 * inv, e3 * inv);
}

// Sum fp32 split-K partials -> fp16
__global__ void reduce_split(const float* __restrict__ in,
                             __half* __restrict__ out, int per, int nsplit,
                             size_t total) {
    size_t i = (size_t)blockIdx.x * blockDim.x + threadIdx.x;
    if (i >= total) return;
    size_t b = i / per;
    size_t r = i - b * per;
    const float* src = in + b * (size_t)nsplit * per + r;
    float s = 0.f;
    for (int ss = 0; ss < nsplit; ss++) s += src[(size_t)ss * per];
    out[i] = __float2half_rn(s);
}

// Fused fp32->fp16 conversion of all 7 weight tensors (packed layout).
__global__ void convert_weights(const float* __restrict__ wp1,
                                const float* __restrict__ wp2,
                                const float* __restrict__ wo1,
                                const float* __restrict__ wo2,
                                const float* __restrict__ wd,
                                const float* __restrict__ wu,
                                const float* __restrict__ wout,
                                __half* __restrict__ out) {
    int i = (blockIdx.x * blockDim.x + threadIdx.x) * 4;
    if (i >= 1179648) return;
    const float* src;
    int local;
    if (i < 131072)      { src = wp1;  local = i; }
    else if (i < 196608) { src = wp2;  local = i - 131072; }
    else if (i < 327680) { src = wo1;  local = i - 196608; }
    else if (i < 393216) { src = wo2;  local = i - 327680; }
    else if (i < 524288) { src = wd;   local = i - 393216; }
    else if (i < 655360) { src = wu;   local = i - 524288; }
    else                 { src = wout; local = i - 655360; }
    float4 v = *(const float4*)&src[local];
    *(__half2*)&out[i] = __floats2half2_rn(v.x, v.y);
    *(__half2*)&out[i + 2] = __floats2half2_rn(v.z, v.w);
}

// ---------------------------------------------------------------------------
// smem sizes (bytes, 2 stages)
static constexpr int SM_FF = 2 * (128 * 144 + 64 * 272);   // 71680
static constexpr int SM_FT = 2 * (128 * 144 + 128 * 144);  // 73728
static constexpr int SM_TF = 2 * (64 * 272 + 64 * 272);    // 69632

extern "C" void kernel_launch(void* const* d_in, const int* in_sizes, int n_in,
                              void* d_out, int out_size) {
    (void)in_sizes; (void)n_in; (void)out_size;
    const float* feat = (const float*)d_in[0];
    const float* wp1 = (const float*)d_in[2];
    const float* bp1 = (const float*)d_in[3];
    const float* wp2 = (const float*)d_in[4];
    const float* bp2 = (const float*)d_in[5];
    const float* wo1 = (const float*)d_in[6];
    const float* bo1 = (const float*)d_in[7];
    const float* wo2 = (const float*)d_in[8];
    const float* bo2 = (const float*)d_in[9];
    const float* wd  = (const float*)d_in[10];
    const float* bd  = (const float*)d_in[11];
    const float* wu  = (const float*)d_in[12];
    const float* bu  = (const float*)d_in[13];
    const float* wout = (const float*)d_in[14];
    const float* bout = (const float*)d_in[15];
    float* outp = (float*)d_out;

    __half *featH, *pwH, *simH, *uH, *t1H, *qH, *ctxH, *c1H, *kmH, *vH, *wH;
    float* splitF;
    cudaGetSymbolAddress((void**)&featH, g_featH);
    cudaGetSymbolAddress((void**)&pwH, g_pwH);
    cudaGetSymbolAddress((void**)&simH, g_simH);
    cudaGetSymbolAddress((void**)&uH, g_uH);
    cudaGetSymbolAddress((void**)&t1H, g_t1H);
    cudaGetSymbolAddress((void**)&qH, g_qH);
    cudaGetSymbolAddress((void**)&ctxH, g_ctxH);
    cudaGetSymbolAddress((void**)&c1H, g_c1H);
    cudaGetSymbolAddress((void**)&kmH, g_kmH);
    cudaGetSymbolAddress((void**)&vH, g_vH);
    cudaGetSymbolAddress((void**)&wH, g_wH);
    cudaGetSymbolAddress((void**)&splitF, g_split);
    __half* wp1H = wH;               // 131072
    __half* wp2H = wH + 131072;      // 65536
    __half* wo1H = wH + 196608;      // 131072
    __half* wo2H = wH + 327680;      // 65536
    __half* wdH  = wH + 393216;      // 131072
    __half* wuH  = wH + 524288;      // 131072
    __half* woutH = wH + 655360;     // 524288

    const size_t sBN = (size_t)CDIM * NDIM;
    const size_t sKN = (size_t)KEYD * NDIM;
    const size_t sCC = (size_t)CDIM * CDIM;
    const size_t sKC = (size_t)KEYD * CDIM;

    cudaFuncSetAttribute(softmax_rows16k,
                         cudaFuncAttributeMaxDynamicSharedMemorySize, 65536);
    cudaFuncSetAttribute(gemm_f16<false, false, false>,
                         cudaFuncAttributeMaxDynamicSharedMemorySize, SM_FF);
    cudaFuncSetAttribute(gemm_f16<false, false, true>,
                         cudaFuncAttributeMaxDynamicSharedMemorySize, SM_FF);
    cudaFuncSetAttribute(gemm_f16<false, true, false>,
                         cudaFuncAttributeMaxDynamicSharedMemorySize, SM_FT);
    cudaFuncSetAttribute(gemm_f16<true, false, false>,
                         cudaFuncAttributeMaxDynamicSharedMemorySize, SM_TF);

    // 0) all weight conversions in one launch
    convert_weights<<<1152, 256>>>(wp1, wp2, wo1, wo2, wd, wu, wout, wH);

    // 1) pwH = softmax(feat rows); featH = fp16(feat)
    softmax_rows16k<<<BATCH * CDIM, 256, 65536>>>(feat, pwH, featH);

    // 2) context partials = featH * pwH^T (split-K=4, single wave) -> splitF
    gemm_f16<false, true, false><<<dim3(4, 4, BATCH * 4), 128, SM_FT>>>(
        featH, sBN, NDIM, pwH, sBN, NDIM, nullptr, 0,
        splitF, sCC, CDIM, nullptr, 1.f, 0, 0, NDIM, 4);
    // 3) reduce -> ctxH
    {
        size_t total = (size_t)BATCH * sCC;
        reduce_split<<<(unsigned)((total + 255) / 256), 256>>>(
            splitF, ctxH, (int)sCC, 4, total);
    }
    // 4) t1 = relu(wp1 @ x + bp1) -> t1H [B,256,N]
    gemm_f16<false, false, false><<<dim3(128, 2, BATCH), 128, SM_FF>>>(
        wp1H, 0, CDIM, featH, sBN, NDIM, nullptr, 0,
        t1H, sKN, NDIM, bp1, 1.f, 1, 1, CDIM, 1);
    // 5) q = relu(wp2 @ t1 + bp2) -> qH [B,256,N]
    gemm_f16<false, false, false><<<dim3(128, 2, BATCH), 128, SM_FF>>>(
        wp2H, 0, KEYD, t1H, sKN, NDIM, nullptr, 0,
        qH, sKN, NDIM, bp2, 1.f, 1, 1, KEYD, 1);
    // 6) c1 = relu(wo1 @ context + bo1) -> c1H [B,256,512]
    gemm_f16<false, false, false><<<dim3(4, 2, BATCH), 128, SM_FF>>>(
        wo1H, 0, CDIM, ctxH, sCC, CDIM, nullptr, 0,
        c1H, sKC, CDIM, bo1, 1.f, 1, 1, CDIM, 1);
    // 7) km = relu(wo2 @ c1 + bo2) -> kmH [B,256,512]
    gemm_f16<false, false, false><<<dim3(4, 2, BATCH), 128, SM_FF>>>(
        wo2H, 0, KEYD, c1H, sKC, CDIM, nullptr, 0,
        kmH, sKC, CDIM, bo2, 1.f, 1, 1, KEYD, 1);
    // 8) v = relu(wd @ context + bd) -> vH [B,256,512]
    gemm_f16<false, false, false><<<dim3(4, 2, BATCH), 128, SM_FF>>>(
        wdH, 0, CDIM, ctxH, sCC, CDIM, nullptr, 0,
        vH, sKC, CDIM, bd, 1.f, 1, 1, CDIM, 1);
    // 9) sim = (q^T @ km) * KEY^-0.5 -> simH [B,N,512]
    gemm_f16<true, false, false><<<dim3(4, 128, BATCH), 128, SM_TF>>>(
        qH, sKN, NDIM, kmH, sKC, CDIM, nullptr, 0,
        simH, sBN, CDIM, nullptr, 0.0625f, 0, 1, KEYD, 1);
    // 10) softmax over K=512 (in place, fp16)
    softmax_k512h<<<BATCH * NDIM, 128>>>(simH);
    // 11) attn ctx = v @ sim^T -> t1H [B,256,N]
    gemm_f16<false, true, false><<<dim3(128, 2, BATCH), 128, SM_FT>>>(
        vH, sKC, CDIM, simH, sBN, CDIM, nullptr, 0,
        t1H, sKN, NDIM, nullptr, 1.f, 0, 1, CDIM, 1);
    // 12) ctx_up = relu(wu @ attn_ctx + bu) -> uH [B,512,N]
    gemm_f16<false, false, false><<<dim3(128, 4, BATCH), 128, SM_FF>>>(
        wuH, 0, KEYD, t1H, sKN, NDIM, nullptr, 0,
        uH, sBN, NDIM, bu, 1.f, 1, 1, KEYD, 1);
    // 13) out = relu(wout @ concat(ctx_up, x) + bout) -> d_out (fp32)
    gemm_f16<false, false, true><<<dim3(128, 4, BATCH), 128, SM_FF>>>(
        woutH, 0, 2 * CDIM, uH, sBN, NDIM, featH, CDIM,
        outp, sBN, NDIM, bout, 1.f, 1, 0, 2 * CDIM, 1);
}

// round 10
// speedup vs baseline: 1.0762x; 1.0735x over previous
#include <cuda_runtime.h>
#include <cuda_fp16.h>
#include <cstdint>
#include <cstddef>

// ---------------------------------------------------------------------------
// OCR head on GB300 — Round 10: mainloop is at the mma.sync HMMA ceiling
// (three neutral scheduling experiments), so this round optimizes the
// TIMELINE: stream-forked context chain overlapped with the q chain inside
// graph capture, stages 6+8 merged into one stacked GEMM. GEMM body = R9.
// ---------------------------------------------------------------------------

#define BATCH 4
#define CDIM 512
#define NDIM 16384
#define KEYD 256

// fp16 buffers
__device__ __half g_featH[33554432];  // feat   [B,512,N]
__device__ __half g_pwH[33554432];    // softmax(feat) [B,512,N]
__device__ __half g_simH[33554432];   // sim    [B,N,512]
__device__ __half g_uH[33554432];     // ctx_up [B,512,N]
__device__ __half g_t1H[16777216];    // t1 [B,256,N]; later attn ctx
__device__ __half g_qH[16777216];     // q  [B,256,N]
__device__ __half g_ctxH[1048576];    // context [B,512,512]
__device__ __half g_cvH[1048576];     // [B, (c1:256 | v:256), 512]
__device__ __half g_kmH[524288];      // [B,256,512]
__device__ __half g_wH[1179648];      // converted weights (packed)
__device__ float g_biasCat[512];      // [bo1 ; bd]
__device__ float g_split[16777216];   // split-K partials

// ---------------------------------------------------------------------------
__device__ __forceinline__ void mma_f16(float c[4], const uint32_t a[4],
                                        const uint32_t b[2]) {
    asm volatile(
        "mma.sync.aligned.m16n8k16.row.col.f32.f16.f16.f32 "
        "{%0,%1,%2,%3}, {%4,%5,%6,%7}, {%8,%9}, {%0,%1,%2,%3};"
        : "+f"(c[0]), "+f"(c[1]), "+f"(c[2]), "+f"(c[3])
        : "r"(a[0]), "r"(a[1]), "r"(a[2]), "r"(a[3]), "r"(b[0]), "r"(b[1]));
}
__device__ __forceinline__ void cp16(uint32_t dst, const void* src) {
    asm volatile("cp.async.cg.shared.global [%0], [%1], 16;\n"
                 :: "r"(dst), "l"(src));
}
__device__ __forceinline__ void cp_commit() {
    asm volatile("cp.async.commit_group;\n" ::: "memory");
}
__device__ __forceinline__ void cp_wait0() {
    asm volatile("cp.async.wait_group 0;\n" ::: "memory");
}
__device__ __forceinline__ void cp_wait_all() {
    asm volatile("cp.async.wait_all;\n" ::: "memory");
}
__device__ __forceinline__ void ldsm_x4(uint32_t& r0, uint32_t& r1,
                                        uint32_t& r2, uint32_t& r3,
                                        uint32_t addr) {
    asm volatile("ldmatrix.sync.aligned.m8n8.x4.shared.b16 {%0,%1,%2,%3}, [%4];"
                 : "=r"(r0), "=r"(r1), "=r"(r2), "=r"(r3) : "r"(addr));
}
__device__ __forceinline__ void ldsm_x4_t(uint32_t& r0, uint32_t& r1,
                                          uint32_t& r2, uint32_t& r3,
                                          uint32_t addr) {
    asm volatile("ldmatrix.sync.aligned.m8n8.x4.trans.shared.b16 {%0,%1,%2,%3}, [%4];"
                 : "=r"(r0), "=r"(r1), "=r"(r2), "=r"(r3) : "r"(addr));
}

// ---------------------------------------------------------------------------
// fp16 batched GEMM (R9 body): C[m,n]=act(alpha*sum_k opA(m,k)opB(k,n)+bias[m])
// TA: A [K,M] else [M,K]; TB: B [N,K] else [K,N]. CONCAT: B k>=ksplitB from B2.
// CTA 128x128, BK=64, 128 thr, warp tile 64x64, 2-stage cp.async + frag pipe.
// ---------------------------------------------------------------------------
template <bool TA, bool TB, bool CONCAT>
__global__ void __launch_bounds__(128, 2)
gemm_f16(const __half* __restrict__ A, size_t sA, int lda,
         const __half* __restrict__ B, size_t sB, int ldb,
         const __half* __restrict__ B2, int ksplitB,
         void* __restrict__ Cv, size_t sCz, int ldc,
         const float* __restrict__ bias, float alpha, int doRelu, int outHalf,
         int K, int nsplit) {
    constexpr int SA_ROW = 144;
    constexpr int SKM_ROW = 272;
    constexpr int ASZ = TA ? 64 * SKM_ROW : 128 * SA_ROW;
    constexpr int BSZ = TB ? 128 * SA_ROW : 64 * SKM_ROW;
    constexpr int STG = ASZ + BSZ;

    extern __shared__ __align__(16) char smem[];
    uint32_t base = (uint32_t)__cvta_generic_to_shared(smem);

    int z = blockIdx.z;
    int b = z / nsplit;
    int sidx = z - b * nsplit;
    int kchunk = K / nsplit;
    int kbeg = sidx * kchunk;
    int niter = kchunk >> 6;

    const __half* Ab = A + (size_t)b * sA;
    const __half* Bb = B + (size_t)b * sB;
    const __half* B2b = CONCAT ? (B2 + (size_t)b * sB) : (const __half*)nullptr;

    int m0 = blockIdx.y * 128;
    int n0 = blockIdx.x * 128;
    int tid = threadIdx.x;
    int warp = tid >> 5, lane = tid & 31;
    int g = lane >> 2, r = lane & 3;
    int wm = warp & 1, wn = warp >> 1;
    int warp_m0 = wm * 64, warp_n0 = wn * 64;

    int mo8 = (lane & 7) + ((lane >> 3) & 1) * 8;
    int khalf = lane >> 4;
    int kq = (lane & 7) + ((lane >> 4) & 1) * 8;
    int chalf = (lane >> 3) & 1;

    float acc[4][8][4];
    #pragma unroll
    for (int i = 0; i < 4; i++)
        #pragma unroll
        for (int j = 0; j < 8; j++)
            #pragma unroll
            for (int e = 0; e < 4; e++) acc[i][j][e] = 0.f;

    auto prefetch = [&](int st, int k0) {
        uint32_t ab = base + st * STG;
        uint32_t bb = ab + ASZ;
        if (TA) {
            #pragma unroll
            for (int p = 0; p < 8; p++) {
                int idx = tid + p * 128;
                int row = idx >> 4, mc = idx & 15;
                cp16(ab + row * SKM_ROW + mc * 16,
                     Ab + (size_t)(k0 + row) * lda + m0 + mc * 8);
            }
        } else {
            #pragma unroll
            for (int p = 0; p < 8; p++) {
                int idx = tid + p * 128;
                int row = idx >> 3, kc = idx & 7;
                cp16(ab + row * SA_ROW + kc * 16,
                     Ab + (size_t)(m0 + row) * lda + k0 + kc * 8);
            }
        }
        if (TB) {
            #pragma unroll
            for (int p = 0; p < 8; p++) {
                int idx = tid + p * 128;
                int row = idx >> 3, kc = idx & 7;
                cp16(bb + row * SA_ROW + kc * 16,
                     Bb + (size_t)(n0 + row) * ldb + k0 + kc * 8);
            }
        } else {
            #pragma unroll
            for (int p = 0; p < 8; p++) {
                int idx = tid + p * 128;
                int row = idx >> 4, nc = idx & 15;
                int kr = k0 + row;
                const __half* src;
                if (CONCAT && kr >= ksplitB)
                    src = B2b + (size_t)(kr - ksplitB) * ldb + n0 + nc * 8;
                else
                    src = Bb + (size_t)kr * ldb + n0 + nc * 8;
                cp16(bb + row * SKM_ROW + nc * 16, src);
            }
        }
        cp_commit();
    };

    prefetch(0, kbeg);

    uint32_t af[2][4][4], bf[2][8][2];

    for (int it = 0; it < niter; it++) {
        int st = it & 1;
        cp_wait0();
        __syncthreads();
        if (it + 1 < niter) prefetch(st ^ 1, kbeg + (it + 1) * 64);

        uint32_t ab = base + st * STG;
        uint32_t bb = ab + ASZ;

        auto load_frags = [&](int fb, int ks) {
            if (TA) {
                #pragma unroll
                for (int i = 0; i < 4; i++) {
                    uint32_t addr = ab + (ks * 16 + kq) * SKM_ROW +
                                    (warp_m0 + i * 16) * 2 + chalf * 16;
                    ldsm_x4_t(af[fb][i][0], af[fb][i][1],
                              af[fb][i][2], af[fb][i][3], addr);
                }
            } else {
                #pragma unroll
                for (int i = 0; i < 4; i++) {
                    uint32_t addr = ab + (warp_m0 + i * 16 + mo8) * SA_ROW +
                                    ks * 32 + khalf * 16;
                    ldsm_x4(af[fb][i][0], af[fb][i][1],
                            af[fb][i][2], af[fb][i][3], addr);
                }
            }
            if (TB) {
                #pragma unroll
                for (int jj = 0; jj < 4; jj++) {
                    uint32_t addr = bb + (warp_n0 + jj * 16 + mo8) * SA_ROW +
                                    ks * 32 + khalf * 16;
                    ldsm_x4(bf[fb][2 * jj][0], bf[fb][2 * jj + 1][0],
                            bf[fb][2 * jj][1], bf[fb][2 * jj + 1][1], addr);
                }
            } else {
                #pragma unroll
                for (int jj = 0; jj < 4; jj++) {
                    uint32_t addr = bb + (ks * 16 + kq) * SKM_ROW +
                                    (warp_n0 + jj * 16) * 2 + chalf * 16;
                    ldsm_x4_t(bf[fb][2 * jj][0], bf[fb][2 * jj + 1][0],
                              bf[fb][2 * jj][1], bf[fb][2 * jj + 1][1], addr);
                }
            }
        };

        load_frags(0, 0);
        #pragma unroll
        for (int ks = 0; ks < 4; ks++) {
            int cur = ks & 1;
            if (ks < 3) load_frags(cur ^ 1, ks + 1);
            #pragma unroll
            for (int i = 0; i < 4; i++)
                #pragma unroll
                for (int j = 0; j < 8; j++)
                    mma_f16(acc[i][j], af[cur][i], bf[cur][j]);
        }
        __syncthreads();
    }

    cp_wait_all();

    __half* Ch = (__half*)Cv + (size_t)z * sCz;
    float* Cf = (float*)Cv + (size_t)z * sCz;
    #pragma unroll
    for (int i = 0; i < 4; i++) {
        int m = m0 + warp_m0 + i * 16 + g;
        float bv0 = bias ? bias[m] : 0.f;
        float bv8 = bias ? bias[m + 8] : 0.f;
        #pragma unroll
        for (int j = 0; j < 8; j++) {
            int n = n0 + warp_n0 + j * 8 + 2 * r;
            float x0 = acc[i][j][0] * alpha + bv0;
            float x1 = acc[i][j][1] * alpha + bv0;
            float x2 = acc[i][j][2] * alpha + bv8;
            float x3 = acc[i][j][3] * alpha + bv8;
            if (doRelu) {
                x0 = fmaxf(x0, 0.f); x1 = fmaxf(x1, 0.f);
                x2 = fmaxf(x2, 0.f); x3 = fmaxf(x3, 0.f);
            }
            if (outHalf) {
                *(__half2*)&Ch[(size_t)m * ldc + n] = __floats2half2_rn(x0, x1);
                *(__half2*)&Ch[(size_t)(m + 8) * ldc + n] = __floats2half2_rn(x2, x3);
            } else {
                *(float2*)&Cf[(size_t)m * ldc + n] = make_float2(x0, x1);
                *(float2*)&Cf[(size_t)(m + 8) * ldc + n] = make_float2(x2, x3);
            }
        }
    }
}

// ---------------------------------------------------------------------------
__global__ void softmax_rows16k(const float* __restrict__ x,
                                __half* __restrict__ pwout,
                                __half* __restrict__ xh) {
    extern __shared__ float srow[];
    __shared__ float red[256];
    const int NC = NDIM;
    size_t row = blockIdx.x;
    const float* xr = x + row * (size_t)NC;
    __half* pwr = pwout + row * (size_t)NC;
    __half* xhr = xh + row * (size_t)NC;
    int tid = threadIdx.x;

    float m = -3.4e38f;
    for (int i = tid * 4; i < NC; i += 1024) {
        float4 v = *(const float4*)&xr[i];
        *(float4*)&srow[i] = v;
        *(__half2*)&xhr[i] = __floats2half2_rn(v.x, v.y);
        *(__half2*)&xhr[i + 2] = __floats2half2_rn(v.z, v.w);
        m = fmaxf(m, fmaxf(fmaxf(v.x, v.y), fmaxf(v.z, v.w)));
    }
    red[tid] = m;
    __syncthreads();
    for (int s = 128; s > 0; s >>= 1) {
        if (tid < s) red[tid] = fmaxf(red[tid], red[tid + s]);
        __syncthreads();
    }
    m = red[0];
    __syncthreads();

    float sum = 0.f;
    for (int i = tid * 4; i < NC; i += 1024) {
        float4 v = *(float4*)&srow[i];
        v.x = __expf(v.x - m); v.y = __expf(v.y - m);
        v.z = __expf(v.z - m); v.w = __expf(v.w - m);
        *(float4*)&srow[i] = v;
        sum += v.x + v.y + v.z + v.w;
    }
    red[tid] = sum;
    __syncthreads();
    for (int s = 128; s > 0; s >>= 1) {
        if (tid < s) red[tid] += red[tid + s];
        __syncthreads();
    }
    float inv = 1.f / red[0];

    for (int i = tid * 4; i < NC; i += 1024) {
        float4 v = *(float4*)&srow[i];
        *(__half2*)&pwr[i] = __floats2half2_rn(v.x * inv, v.y * inv);
        *(__half2*)&pwr[i + 2] = __floats2half2_rn(v.z * inv, v.w * inv);
    }
}

__global__ void softmax_k512h(__half* __restrict__ sim) {
    __shared__ float redm[4];
    __shared__ float reds[4];
    size_t row = blockIdx.x;
    __half2* rp = (__half2*)(sim + row * 512);
    int tid = threadIdx.x;

    __half2 h0 = rp[tid * 2], h1 = rp[tid * 2 + 1];
    float2 f0 = __half22float2(h0), f1 = __half22float2(h1);
    float m = fmaxf(fmaxf(f0.x, f0.y), fmaxf(f1.x, f1.y));
    #pragma unroll
    for (int o = 16; o > 0; o >>= 1)
        m = fmaxf(m, __shfl_xor_sync(0xffffffffu, m, o));
    if ((tid & 31) == 0) redm[tid >> 5] = m;
    __syncthreads();
    m = fmaxf(fmaxf(redm[0], redm[1]), fmaxf(redm[2], redm[3]));

    float e0 = __expf(f0.x - m), e1 = __expf(f0.y - m);
    float e2 = __expf(f1.x - m), e3 = __expf(f1.y - m);
    float s = e0 + e1 + e2 + e3;
    #pragma unroll
    for (int o = 16; o > 0; o >>= 1)
        s += __shfl_xor_sync(0xffffffffu, s, o);
    if ((tid & 31) == 0) reds[tid >> 5] = s;
    __syncthreads();
    float inv = 1.f / (reds[0] + reds[1] + reds[2] + reds[3]);

    rp[tid * 2] = __floats2half2_rn(e0 * inv, e1 * inv);
    rp[tid * 2 + 1] = __floats2half2_rn(e2 * inv, e3 * inv);
}

__global__ void reduce_split(const float* __restrict__ in,
                             __half* __restrict__ out, int per, int nsplit,
                             size_t total) {
    size_t i = (size_t)blockIdx.x * blockDim.x + threadIdx.x;
    if (i >= total) return;
    size_t b = i / per;
    size_t r = i - b * per;
    const float* src = in + b * (size_t)nsplit * per + r;
    float s = 0.f;
    for (int ss = 0; ss < nsplit; ss++) s += src[(size_t)ss * per];
    out[i] = __float2half_rn(s);
}

// fp32->fp16 all weights (packed: wp1|wp2|wo1|wd|wo2|wu|wout) + bias concat.
__global__ void convert_weights(const float* __restrict__ wp1,
                                const float* __restrict__ wp2,
                                const float* __restrict__ wo1,
                                const float* __restrict__ wo2,
                                const float* __restrict__ wd,
                                const float* __restrict__ wu,
                                const float* __restrict__ wout,
                                const float* __restrict__ bo1,
                                const float* __restrict__ bd,
                                __half* __restrict__ out,
                                float* __restrict__ bcat) {
    int t = blockIdx.x * blockDim.x + threadIdx.x;
    if (t < 256) bcat[t] = bo1[t];
    else if (t < 512) bcat[t] = bd[t - 256];
    int i = t * 4;
    if (i >= 1179648) return;
    const float* src;
    int local;
    if (i < 131072)      { src = wp1;  local = i; }
    else if (i < 196608) { src = wp2;  local = i - 131072; }
    else if (i < 327680) { src = wo1;  local = i - 196608; }
    else if (i < 458752) { src = wd;   local = i - 327680; }
    else if (i < 524288) { src = wo2;  local = i - 458752; }
    else if (i < 655360) { src = wu;   local = i - 524288; }
    else                 { src = wout; local = i - 655360; }
    float4 v = *(const float4*)&src[local];
    *(__half2*)&out[i] = __floats2half2_rn(v.x, v.y);
    *(__half2*)&out[i + 2] = __floats2half2_rn(v.z, v.w);
}

// ---------------------------------------------------------------------------
static constexpr int SM_FF = 2 * (128 * 144 + 64 * 272);   // 71680
static constexpr int SM_FT = 2 * (128 * 144 + 128 * 144);  // 73728
static constexpr int SM_TF = 2 * (64 * 272 + 64 * 272);    // 69632

extern "C" void kernel_launch(void* const* d_in, const int* in_sizes, int n_in,
                              void* d_out, int out_size) {
    (void)in_sizes; (void)n_in; (void)out_size;
    const float* feat = (const float*)d_in[0];
    const float* wp1 = (const float*)d_in[2];
    const float* bp1 = (const float*)d_in[3];
    const float* wp2 = (const float*)d_in[4];
    const float* bp2 = (const float*)d_in[5];
    const float* wo1 = (const float*)d_in[6];
    const float* bo1 = (const float*)d_in[7];
    const float* wo2 = (const float*)d_in[8];
    const float* bo2 = (const float*)d_in[9];
    const float* wd  = (const float*)d_in[10];
    const float* bd  = (const float*)d_in[11];
    const float* wu  = (const float*)d_in[12];
    const float* bu  = (const float*)d_in[13];
    const float* wout = (const float*)d_in[14];
    const float* bout = (const float*)d_in[15];
    float* outp = (float*)d_out;

    __half *featH, *pwH, *simH, *uH, *t1H, *qH, *ctxH, *cvH, *kmH, *wH;
    float *splitF, *bcat;
    cudaGetSymbolAddress((void**)&featH, g_featH);
    cudaGetSymbolAddress((void**)&pwH, g_pwH);
    cudaGetSymbolAddress((void**)&simH, g_simH);
    cudaGetSymbolAddress((void**)&uH, g_uH);
    cudaGetSymbolAddress((void**)&t1H, g_t1H);
    cudaGetSymbolAddress((void**)&qH, g_qH);
    cudaGetSymbolAddress((void**)&ctxH, g_ctxH);
    cudaGetSymbolAddress((void**)&cvH, g_cvH);
    cudaGetSymbolAddress((void**)&kmH, g_kmH);
    cudaGetSymbolAddress((void**)&wH, g_wH);
    cudaGetSymbolAddress((void**)&splitF, g_split);
    cudaGetSymbolAddress((void**)&bcat, g_biasCat);
    __half* wp1H = wH;               // 131072
    __half* wp2H = wH + 131072;      // 65536
    __half* wcatH = wH + 196608;     // 262144 (wo1 rows 0-255 | wd rows 256-511)
    __half* wo2H = wH + 458752;      // 65536
    __half* wuH  = wH + 524288;      // 131072
    __half* woutH = wH + 655360;     // 524288

    const size_t sBN = (size_t)CDIM * NDIM;
    const size_t sKN = (size_t)KEYD * NDIM;
    const size_t sCC = (size_t)CDIM * CDIM;    // 262144
    const size_t sKC = (size_t)KEYD * CDIM;    // 131072

    // one-time host-side resources (handles only; no device memory)
    static cudaStream_t sCtx = nullptr;
    static cudaEvent_t evFork = nullptr, evJoin = nullptr;
    if (sCtx == nullptr) {
        cudaStreamCreateWithFlags(&sCtx, cudaStreamNonBlocking);
        cudaEventCreateWithFlags(&evFork, cudaEventDisableTiming);
        cudaEventCreateWithFlags(&evJoin, cudaEventDisableTiming);
    }

    cudaFuncSetAttribute(softmax_rows16k,
                         cudaFuncAttributeMaxDynamicSharedMemorySize, 65536);
    cudaFuncSetAttribute(gemm_f16<false, false, false>,
                         cudaFuncAttributeMaxDynamicSharedMemorySize, SM_FF);
    cudaFuncSetAttribute(gemm_f16<false, false, true>,
                         cudaFuncAttributeMaxDynamicSharedMemorySize, SM_FF);
    cudaFuncSetAttribute(gemm_f16<false, true, false>,
                         cudaFuncAttributeMaxDynamicSharedMemorySize, SM_FT);
    cudaFuncSetAttribute(gemm_f16<true, false, false>,
                         cudaFuncAttributeMaxDynamicSharedMemorySize, SM_TF);

    // 0) weights + bias concat
    convert_weights<<<1152, 256>>>(wp1, wp2, wo1, wo2, wd, wu, wout,
                                   bo1, bd, wH, bcat);
    // 1) pwH = softmax(feat rows); featH = fp16(feat)
    softmax_rows16k<<<BATCH * CDIM, 256, 65536>>>(feat, pwH, featH);

    // ---- fork: context chain on sCtx, q chain on default stream ----
    cudaEventRecord(evFork, 0);
    cudaStreamWaitEvent(sCtx, evFork, 0);

    // [sCtx] 2) context partials = featH * pwH^T (split-K=4)
    gemm_f16<false, true, false><<<dim3(4, 4, BATCH * 4), 128, SM_FT, sCtx>>>(
        featH, sBN, NDIM, pwH, sBN, NDIM, nullptr, 0,
        splitF, sCC, CDIM, nullptr, 1.f, 0, 0, NDIM, 4);
    // [sCtx] 3) reduce -> ctxH
    {
        size_t total = (size_t)BATCH * sCC;
        reduce_split<<<(unsigned)((total + 255) / 256), 256, 0, sCtx>>>(
            splitF, ctxH, (int)sCC, 4, total);
    }
    // [sCtx] 6+8) [c1;v] = relu([wo1;wd] @ context + [bo1;bd]) -> cvH
    gemm_f16<false, false, false><<<dim3(4, 4, BATCH), 128, SM_FF, sCtx>>>(
        wcatH, 0, CDIM, ctxH, sCC, CDIM, nullptr, 0,
        cvH, sCC, CDIM, bcat, 1.f, 1, 1, CDIM, 1);
    // [sCtx] 7) km = relu(wo2 @ c1 + bo2) -> kmH
    gemm_f16<false, false, false><<<dim3(4, 2, BATCH), 128, SM_FF, sCtx>>>(
        wo2H, 0, KEYD, cvH, sCC, CDIM, nullptr, 0,
        kmH, sKC, CDIM, bo2, 1.f, 1, 1, KEYD, 1);
    cudaEventRecord(evJoin, sCtx);

    // [s0] 4) t1 = relu(wp1 @ x + bp1)
    gemm_f16<false, false, false><<<dim3(128, 2, BATCH), 128, SM_FF>>>(
        wp1H, 0, CDIM, featH, sBN, NDIM, nullptr, 0,
        t1H, sKN, NDIM, bp1, 1.f, 1, 1, CDIM, 1);
    // [s0] 5) q = relu(wp2 @ t1 + bp2)
    gemm_f16<false, false, false><<<dim3(128, 2, BATCH), 128, SM_FF>>>(
        wp2H, 0, KEYD, t1H, sKN, NDIM, nullptr, 0,
        qH, sKN, NDIM, bp2, 1.f, 1, 1, KEYD, 1);

    // ---- join ----
    cudaStreamWaitEvent(0, evJoin, 0);

    // 9) sim = (q^T @ km) * KEY^-0.5
    gemm_f16<true, false, false><<<dim3(4, 128, BATCH), 128, SM_TF>>>(
        qH, sKN, NDIM, kmH, sKC, CDIM, nullptr, 0,
        simH, sBN, CDIM, nullptr, 0.0625f, 0, 1, KEYD, 1);
    // 10) softmax over K=512
    softmax_k512h<<<BATCH * NDIM, 128>>>(simH);
    // 11) attn ctx = v @ sim^T   (v = cvH rows 256-511)
    gemm_f16<false, true, false><<<dim3(128, 2, BATCH), 128, SM_FT>>>(
        cvH + 131072, sCC, CDIM, simH, sBN, CDIM, nullptr, 0,
        t1H, sKN, NDIM, nullptr, 1.f, 0, 1, CDIM, 1);
    // 12) ctx_up = relu(wu @ attn_ctx + bu)
    gemm_f16<false, false, false><<<dim3(128, 4, BATCH), 128, SM_FF>>>(
        wuH, 0, KEYD, t1H, sKN, NDIM, nullptr, 0,
        uH, sBN, NDIM, bu, 1.f, 1, 1, KEYD, 1);
    // 13) out = relu(wout @ concat(ctx_up, x) + bout) -> d_out (fp32)
    gemm_f16<false, false, true><<<dim3(128, 4, BATCH), 128, SM_FF>>>(
        woutH, 0, 2 * CDIM, uH, sBN, NDIM, featH, CDIM,
        outp, sBN, NDIM, bout, 1.f, 1, 0, 2 * CDIM, 1);
}